// round 16
// baseline (speedup 1.0000x reference)
#include <cuda_runtime.h>
#include <cuda_bf16.h>
#include <cuda_fp16.h>
#include <cstdint>
#include <math.h>

// ---------------------------------------------------------------------------
// Problem constants
// ---------------------------------------------------------------------------
#define EMB   1024
#define HID   4096
#define BATCH 2
#define SEQT  4096
#define MROWS (BATCH * SEQT)   // 8192
#define EPS_F 1e-6f
#define NCHUNK 32
#define CHUNK  (SEQT / NCHUNK)   // 128  (== M-tile, chunk-aligned)

// ---------------------------------------------------------------------------
// Scratch buffers (static; runtime allocation forbidden)
// ---------------------------------------------------------------------------
__device__ __align__(16) __half g_rh  [(size_t)MROWS * EMB];          //  16 MB
__device__ __align__(16) __half g_w12h[(size_t)(2 * HID) * EMB];      //  16 MB
__device__ __align__(16) __half g_w3h [(size_t)EMB * HID];            //   8 MB
__device__ __align__(16) __half g_ea  [(size_t)MROWS * HID];          //  64 MB exp(a)
__device__ __align__(16) __half g_eb  [(size_t)MROWS * HID];          //  64 MB exp(b)
__device__ __align__(16) __half g_y   [(size_t)MROWS * HID];          //  64 MB y=(sa*sb)/t^2
__device__ __align__(16) float g_pa[(size_t)BATCH * NCHUNK * HID];    //   1 MB
__device__ __align__(16) float g_pb[(size_t)BATCH * NCHUNK * HID];    //   1 MB
__device__ __align__(16) float g_scale[MROWS];                        //  32 KB row scales

// ---------------------------------------------------------------------------
// PTX helpers (plain sm_103-legal)
// ---------------------------------------------------------------------------
__device__ __forceinline__ uint32_t smem_u32(const void* p) {
    uint32_t a;
    asm("{ .reg .u64 t; cvta.to.shared.u64 t, %1; cvt.u32.u64 %0, t; }"
        : "=r"(a) : "l"(p));
    return a;
}
__device__ __forceinline__ void cp16(uint32_t s, const void* g) {
    asm volatile("cp.async.cg.shared.global [%0], [%1], 16;" :: "r"(s), "l"(g));
}
__device__ __forceinline__ void cp_commit() {
    asm volatile("cp.async.commit_group;" ::: "memory");
}
__device__ __forceinline__ void ldsm_x4(uint32_t& r0, uint32_t& r1,
                                        uint32_t& r2, uint32_t& r3, uint32_t addr) {
    asm volatile("ldmatrix.sync.aligned.m8n8.x4.shared.b16 {%0,%1,%2,%3}, [%4];"
                 : "=r"(r0), "=r"(r1), "=r"(r2), "=r"(r3) : "r"(addr));
}
__device__ __forceinline__ void mma16(float& d0, float& d1, float& d2, float& d3,
                                      uint32_t a0, uint32_t a1, uint32_t a2, uint32_t a3,
                                      uint32_t b0, uint32_t b1) {
    asm volatile(
        "mma.sync.aligned.m16n8k16.row.col.f32.f16.f16.f32 "
        "{%0,%1,%2,%3}, {%4,%5,%6,%7}, {%8,%9}, {%0,%1,%2,%3};"
        : "+f"(d0), "+f"(d1), "+f"(d2), "+f"(d3)
        : "r"(a0), "r"(a1), "r"(a2), "r"(a3), "r"(b0), "r"(b1));
}
__device__ __forceinline__ uint32_t sw128(uint32_t off) {
    return off ^ ((off >> 3) & 0x70);
}

// ===========================================================================
// Shared GEMM config: 128x128x64 tiles, 256 threads (8 warps 2x4), 2 CTA/SM.
// Single barrier per chunk (trailing sync proven redundant: iter c writes
// stage (c+2)%3 which was consumed in iter c-1; top-of-loop barrier orders it).
// ===========================================================================
#define BK 64
#define OPB 16384
#define STAGE_BYTES (2 * OPB)
#define NSTAGE 3
#define GEMM_SMEM (NSTAGE * STAGE_BYTES)

__device__ __forceinline__ void issue_tile_loads(
    uint32_t sbase, int st, const __half* Ab, const __half* Bb,
    int koff, int K, int tid)
{
    uint32_t stage = sbase + (uint32_t)st * STAGE_BYTES;
#pragma unroll
    for (int t = 0; t < 4; t++) {
        int idx = tid + t * 256;
        int row = idx >> 3;
        int u   = idx & 7;
        uint32_t sw = sw128((uint32_t)idx << 4);
        cp16(stage       + sw, Ab + (size_t)row * K + koff + u * 8);
        cp16(stage + OPB + sw, Bb + (size_t)row * K + koff + u * 8);
    }
}

// MODE 1: epilogue exp() -> fp16 E0/E1 + per-chunk column sums
// MODE 2: epilogue out = Cadd + S[m]*acc
template <int MODE>
__global__ void __launch_bounds__(256, 2)
hgemm_kernel(const __half* __restrict__ A, const __half* __restrict__ B,
             float* __restrict__ C0,
             const float* __restrict__ Cadd,
             __half* __restrict__ E0, __half* __restrict__ E1,
             float* __restrict__ pa, float* __restrict__ pb,
             const float* __restrict__ S,
             int M, int N, int K, int nsplit)
{
    extern __shared__ char smem[];
    uint32_t sbase = smem_u32(smem);
    const int tid  = threadIdx.x;
    const int wid  = tid >> 5;
    const int lane = tid & 31;
    const int wm   = wid & 1;
    const int wn   = wid >> 1;
    const int bm   = blockIdx.y * 128;
    const int bn   = blockIdx.x * 128;
    const int NC   = K / BK;

    const __half* Ab = A + (size_t)bm * K;
    const __half* Bb = B + (size_t)bn * K;

    float acc[4][4][4];
#pragma unroll
    for (int i = 0; i < 4; i++)
#pragma unroll
        for (int j = 0; j < 4; j++)
#pragma unroll
            for (int q = 0; q < 4; q++) acc[i][j][q] = 0.0f;

    const int a_m  = wm * 64 + (lane & 15);
    const int a_ku = lane >> 4;
    const int b_n  = wn * 32 + (lane & 7) + ((lane >> 4) << 3);
    const int b_ku = (lane >> 3) & 1;

    issue_tile_loads(sbase, 0, Ab, Bb, 0,  K, tid); cp_commit();
    issue_tile_loads(sbase, 1, Ab, Bb, BK, K, tid); cp_commit();

    for (int c = 0; c < NC; c++) {
        if (c + 1 < NC) asm volatile("cp.async.wait_group 1;" ::: "memory");
        else            asm volatile("cp.async.wait_group 0;" ::: "memory");
        __syncthreads();

        if (c + 2 < NC) {
            issue_tile_loads(sbase, (c + 2) % NSTAGE, Ab, Bb, (c + 2) * BK, K, tid);
            cp_commit();
        }

        uint32_t stage = sbase + (uint32_t)(c % NSTAGE) * STAGE_BYTES;
#pragma unroll
        for (int ks = 0; ks < 4; ks++) {
            uint32_t a0[4], a1[4], a2[4], a3[4];
            uint32_t bb0[2], bb1[2], bb2[2], bb3[2];
#pragma unroll
            for (int mf = 0; mf < 4; mf++) {
                int m  = a_m + mf * 16;
                int ku = ks * 2 + a_ku;
                ldsm_x4(a0[mf], a1[mf], a2[mf], a3[mf],
                        stage + sw128((uint32_t)(m * 128 + ku * 16)));
            }
#pragma unroll
            for (int nf2 = 0; nf2 < 2; nf2++) {
                int n  = b_n + nf2 * 16;
                int ku = ks * 2 + b_ku;
                uint32_t r0, r1, r2, r3;
                ldsm_x4(r0, r1, r2, r3,
                        stage + OPB + sw128((uint32_t)(n * 128 + ku * 16)));
                if (nf2 == 0) { bb0[0] = r0; bb0[1] = r1; bb1[0] = r2; bb1[1] = r3; }
                else          { bb2[0] = r0; bb2[1] = r1; bb3[0] = r2; bb3[1] = r3; }
            }
#pragma unroll
            for (int mf = 0; mf < 4; mf++) {
                mma16(acc[mf][0][0], acc[mf][0][1], acc[mf][0][2], acc[mf][0][3],
                      a0[mf], a1[mf], a2[mf], a3[mf], bb0[0], bb0[1]);
                mma16(acc[mf][1][0], acc[mf][1][1], acc[mf][1][2], acc[mf][1][3],
                      a0[mf], a1[mf], a2[mf], a3[mf], bb1[0], bb1[1]);
                mma16(acc[mf][2][0], acc[mf][2][1], acc[mf][2][2], acc[mf][2][3],
                      a0[mf], a1[mf], a2[mf], a3[mf], bb2[0], bb2[1]);
                mma16(acc[mf][3][0], acc[mf][3][1], acc[mf][3][2], acc[mf][3][3],
                      a0[mf], a1[mf], a2[mf], a3[mf], bb3[0], bb3[1]);
            }
        }
        // no trailing sync: next iteration's top barrier provides the ordering
    }

    const int inC0 = (bn < nsplit);
    const int ldc  = inC0 ? nsplit : (N - nsplit);
    const int cb   = inC0 ? bn : bn - nsplit;

    if (MODE == 2) {
#pragma unroll
        for (int mf = 0; mf < 4; mf++) {
            int r0 = bm + wm * 64 + mf * 16 + (lane >> 2);
            int r1 = r0 + 8;
            float s0 = S[r0], s1 = S[r1];
#pragma unroll
            for (int nf = 0; nf < 4; nf++) {
                int col = cb + wn * 32 + nf * 8 + (lane & 3) * 2;
                const float2 x0 = *(const float2*)(Cadd + (size_t)r0 * ldc + col);
                const float2 x1 = *(const float2*)(Cadd + (size_t)r1 * ldc + col);
                float2 v0 = make_float2(fmaf(s0, acc[mf][nf][0], x0.x),
                                        fmaf(s0, acc[mf][nf][1], x0.y));
                float2 v1 = make_float2(fmaf(s1, acc[mf][nf][2], x1.x),
                                        fmaf(s1, acc[mf][nf][3], x1.y));
                *(float2*)(C0 + (size_t)r0 * ldc + col) = v0;
                *(float2*)(C0 + (size_t)r1 * ldc + col) = v1;
            }
        }
    } else {
        // MODE 1: exp in place, store fp16, reduce per-chunk column sums
#pragma unroll
        for (int mf = 0; mf < 4; mf++)
#pragma unroll
            for (int nf = 0; nf < 4; nf++)
#pragma unroll
                for (int q = 0; q < 4; q++)
                    acc[mf][nf][q] = __expf(acc[mf][nf][q]);

        __half* Eb = inC0 ? E0 : E1;
#pragma unroll
        for (int mf = 0; mf < 4; mf++) {
            int r0 = bm + wm * 64 + mf * 16 + (lane >> 2);
            int r1 = r0 + 8;
#pragma unroll
            for (int nf = 0; nf < 4; nf++) {
                int col = cb + wn * 32 + nf * 8 + (lane & 3) * 2;
                *(__half2*)(Eb + (size_t)r0 * ldc + col) =
                    __floats2half2_rn(acc[mf][nf][0], acc[mf][nf][1]);
                *(__half2*)(Eb + (size_t)r1 * ldc + col) =
                    __floats2half2_rn(acc[mf][nf][2], acc[mf][nf][3]);
            }
        }

        float cs[4][2];
#pragma unroll
        for (int nf = 0; nf < 4; nf++) {
            cs[nf][0] = cs[nf][1] = 0.0f;
#pragma unroll
            for (int mf = 0; mf < 4; mf++) {
                cs[nf][0] += acc[mf][nf][0] + acc[mf][nf][2];
                cs[nf][1] += acc[mf][nf][1] + acc[mf][nf][3];
            }
#pragma unroll
            for (int off = 4; off < 32; off <<= 1) {
                cs[nf][0] += __shfl_xor_sync(0xffffffffu, cs[nf][0], off);
                cs[nf][1] += __shfl_xor_sync(0xffffffffu, cs[nf][1], off);
            }
        }
        __syncthreads();             // ensure mainloop smem use is done block-wide
        float* red = (float*)smem;   // stages dead now
        if (lane < 4) {
#pragma unroll
            for (int nf = 0; nf < 4; nf++) {
                int col = wn * 32 + nf * 8 + lane * 2;
                red[wm * 128 + col]     = cs[nf][0];
                red[wm * 128 + col + 1] = cs[nf][1];
            }
        }
        __syncthreads();
        if (tid < 128) {
            int bb = bm / SEQT;
            int ch = (bm % SEQT) / CHUNK;
            float* P = inC0 ? pa : pb;
            P[(size_t)(bb * NCHUNK + ch) * HID + cb + tid] =
                red[tid] + red[128 + tid];
        }
    }
}

// ---------------------------------------------------------------------------
// Block-wide sum reduce
// ---------------------------------------------------------------------------
__device__ __forceinline__ float block_reduce_sum(float v) {
    __shared__ float sh[32];
    int lane = threadIdx.x & 31;
    int wid  = threadIdx.x >> 5;
#pragma unroll
    for (int o = 16; o; o >>= 1) v += __shfl_xor_sync(0xffffffffu, v, o);
    if (lane == 0) sh[wid] = v;
    __syncthreads();
    int nw = blockDim.x >> 5;
    if (wid == 0) {
        v = (lane < nw) ? sh[lane] : 0.0f;
#pragma unroll
        for (int o = 16; o; o >>= 1) v += __shfl_xor_sync(0xffffffffu, v, o);
    }
    return v;
}

// ---------------------------------------------------------------------------
// Fused prep: blocks [0, MROWS) do rmsnorm(x)->fp16; remaining blocks convert
// W1/W2/W3 fp32->fp16 (256 float4s per block).
// ---------------------------------------------------------------------------
__global__ void prep_kernel(const float* __restrict__ x,
                            const float* __restrict__ W1,
                            const float* __restrict__ W2,
                            const float* __restrict__ W3,
                            __half* __restrict__ rh,
                            __half* __restrict__ w12h,
                            __half* __restrict__ w3h,
                            int nv12, int nv3) {
    if (blockIdx.x < MROWS) {
        int row = blockIdx.x;
        const float4* ir = (const float4*)(x + (size_t)row * EMB);
        int nvec = EMB >> 2;
        float ss = 0.0f;
        for (int i = threadIdx.x; i < nvec; i += 256) {
            float4 v = ir[i];
            ss += v.x * v.x + v.y * v.y + v.z * v.z + v.w * v.w;
        }
        ss = block_reduce_sum(ss);
        __shared__ float s_scale;
        if (threadIdx.x == 0) s_scale = rsqrtf(ss / (float)EMB + EPS_F);
        __syncthreads();
        float sc = s_scale;
        __half2* op = (__half2*)(rh + (size_t)row * EMB);
        for (int i = threadIdx.x; i < nvec; i += 256) {
            float4 v = ir[i];
            op[2 * i]     = __floats2half2_rn(v.x * sc, v.y * sc);
            op[2 * i + 1] = __floats2half2_rn(v.z * sc, v.w * sc);
        }
    } else {
        int i = (blockIdx.x - MROWS) * 256 + threadIdx.x;
        const float* src;
        __half2* dst;
        int j;
        if (i < nv12)                { src = W1; dst = (__half2*)w12h;                      j = i; }
        else if (i < 2 * nv12)       { src = W2; dst = (__half2*)(w12h + (size_t)nv12 * 4); j = i - nv12; }
        else if (i < 2 * nv12 + nv3) { src = W3; dst = (__half2*)w3h;                      j = i - 2 * nv12; }
        else return;
        float4 v = ((const float4*)src)[j];
        dst[2 * j]     = __floats2half2_rn(v.x, v.y);
        dst[2 * j + 1] = __floats2half2_rn(v.z, v.w);
    }
}

// ---------------------------------------------------------------------------
// Row rms-scale from fp16 y: scale[row] = rsqrt(mean(y^2) + eps)
// ---------------------------------------------------------------------------
__global__ void rowscale_kernel(const __half* __restrict__ y,
                                float* __restrict__ scale) {
    int row = blockIdx.x;
    const float4* ir = (const float4*)(y + (size_t)row * HID);  // 8 halves per ld
    float ss = 0.0f;
    for (int i = threadIdx.x; i < HID / 8; i += 256) {
        float4 u = ir[i];
        __half2 h0 = *(__half2*)&u.x, h1 = *(__half2*)&u.y;
        __half2 h2 = *(__half2*)&u.z, h3 = *(__half2*)&u.w;
        float2 v0 = __half22float2(h0), v1 = __half22float2(h1);
        float2 v2 = __half22float2(h2), v3 = __half22float2(h3);
        ss += v0.x * v0.x + v0.y * v0.y + v1.x * v1.x + v1.y * v1.y
            + v2.x * v2.x + v2.y * v2.y + v3.x * v3.x + v3.y * v3.y;
    }
    ss = block_reduce_sum(ss);
    if (threadIdx.x == 0) scale[row] = rsqrtf(ss / (float)HID + EPS_F);
}

// ---------------------------------------------------------------------------
// pass2: exclusive prefix over chunk sums (batched loads for MLP)
// ---------------------------------------------------------------------------
__global__ void bar_pass2_kernel(float* __restrict__ pa,
                                 float* __restrict__ pb) {
    int idx = blockIdx.x * 256 + threadIdx.x;
    int bb = idx >> 12;
    int h  = idx & (HID - 1);
    float va[NCHUNK], vb[NCHUNK];
#pragma unroll
    for (int c = 0; c < NCHUNK; c++) {
        va[c] = pa[(size_t)(bb * NCHUNK + c) * HID + h];
        vb[c] = pb[(size_t)(bb * NCHUNK + c) * HID + h];
    }
    float ra = 0.0f, rb = 0.0f;
#pragma unroll
    for (int c = 0; c < NCHUNK; c++) {
        float ta = va[c], tb = vb[c];
        va[c] = ra; vb[c] = rb;
        ra += ta; rb += tb;
    }
#pragma unroll
    for (int c = 0; c < NCHUNK; c++) {
        pa[(size_t)(bb * NCHUNK + c) * HID + h] = va[c];
        pb[(size_t)(bb * NCHUNK + c) * HID + h] = vb[c];
    }
}

// ---------------------------------------------------------------------------
// pass3: within-chunk scan from prefix; y = (sa*sb)/(t+1)^2 in fp16.
// Pure streaming, no cross-thread reduction. 2 channels per thread.
// ---------------------------------------------------------------------------
__global__ void bar_pass3_kernel(const __half* __restrict__ ea,
                                 const __half* __restrict__ eb,
                                 const float* __restrict__ pa,
                                 const float* __restrict__ pb,
                                 __half* __restrict__ y) {
    int h2 = blockIdx.x * 256 + threadIdx.x;   // pair index
    int c  = blockIdx.y;
    int bb = blockIdx.z;
    size_t base = (size_t)bb * SEQT * HID + (size_t)c * CHUNK * HID + h2 * 2;
    const __half2* ap = (const __half2*)(ea + base);
    const __half2* bp = (const __half2*)(eb + base);
    __half2* yp = (__half2*)(y + base);

    int po = (bb * NCHUNK + c) * HID + h2 * 2;
    float sa0 = pa[po], sa1 = pa[po + 1];
    float sb0 = pb[po], sb1 = pb[po + 1];
#pragma unroll 8
    for (int t = 0; t < CHUNK; t++) {
        float2 va = __half22float2(ap[(size_t)t * (HID / 2)]);
        float2 vb = __half22float2(bp[(size_t)t * (HID / 2)]);
        sa0 += va.x; sa1 += va.y;
        sb0 += vb.x; sb1 += vb.y;
        float tf = (float)(c * CHUNK + t + 1);
        float inv = __fdividef(1.0f, tf * tf);
        yp[(size_t)t * (HID / 2)] =
            __floats2half2_rn(sa0 * sb0 * inv, sa1 * sb1 * inv);
    }
}

// ---------------------------------------------------------------------------
// kernel_launch
// ---------------------------------------------------------------------------
extern "C" void kernel_launch(void* const* d_in, const int* in_sizes, int n_in,
                              void* d_out, int out_size) {
    const float* x  = (const float*)d_in[0];
    const float* W1 = (const float*)d_in[1];
    const float* W2 = (const float*)d_in[2];
    const float* W3 = (const float*)d_in[3];
    float* out = (float*)d_out;

    __half *rh, *w12h, *w3h, *ea, *eb, *y_p;
    float *pa_p, *pb_p, *sc_p;
    cudaGetSymbolAddress((void**)&rh,   g_rh);
    cudaGetSymbolAddress((void**)&w12h, g_w12h);
    cudaGetSymbolAddress((void**)&w3h,  g_w3h);
    cudaGetSymbolAddress((void**)&ea,   g_ea);
    cudaGetSymbolAddress((void**)&eb,   g_eb);
    cudaGetSymbolAddress((void**)&y_p,  g_y);
    cudaGetSymbolAddress((void**)&pa_p, g_pa);
    cudaGetSymbolAddress((void**)&pb_p, g_pb);
    cudaGetSymbolAddress((void**)&sc_p, g_scale);

    cudaFuncSetAttribute(hgemm_kernel<1>, cudaFuncAttributeMaxDynamicSharedMemorySize,
                         GEMM_SMEM);
    cudaFuncSetAttribute(hgemm_kernel<2>, cudaFuncAttributeMaxDynamicSharedMemorySize,
                         GEMM_SMEM);

    // 1) fused prep: rmsnorm(x)->fp16 + all weight converts, one launch
    {
        int nv12 = (HID * EMB) / 4;
        int nv3  = (EMB * HID) / 4;
        int wblocks = (2 * nv12 + nv3 + 255) / 256;
        prep_kernel<<<MROWS + wblocks, 256>>>(x, W1, W2, W3, rh, w12h, w3h,
                                              nv12, nv3);
    }

    // 2) fused GEMM1/2 + exp + chunk sums (128x128, 2 CTA/SM)
    hgemm_kernel<1><<<dim3((2 * HID) / 128, MROWS / 128), 256, GEMM_SMEM>>>(
        rh, w12h, nullptr, nullptr, ea, eb, pa_p, pb_p, nullptr,
        MROWS, 2 * HID, EMB, HID);

    // 3) prefix over chunks, then within-chunk streaming scan -> y fp16
    bar_pass2_kernel<<<(BATCH * HID) / 256, 256>>>(pa_p, pb_p);
    {
        dim3 grid(HID / 512, NCHUNK, BATCH);
        bar_pass3_kernel<<<grid, 256>>>(ea, eb, pa_p, pb_p, y_p);
    }

    // 4) per-row rms scales from y
    rowscale_kernel<<<MROWS, 256>>>(y_p, sc_p);

    // 5) out = x + S[m] * (y @ W3^T)
    hgemm_kernel<2><<<dim3(EMB / 128, MROWS / 128), 256, GEMM_SMEM>>>(
        y_p, w3h, out, x, nullptr, nullptr, nullptr, nullptr, sc_p,
        MROWS, EMB, HID, EMB);
}

// round 17
// speedup vs baseline: 1.0048x; 1.0048x over previous
#include <cuda_runtime.h>
#include <cuda_bf16.h>
#include <cuda_fp16.h>
#include <cstdint>
#include <math.h>

// ---------------------------------------------------------------------------
// Problem constants
// ---------------------------------------------------------------------------
#define EMB   1024
#define HID   4096
#define BATCH 2
#define SEQT  4096
#define MROWS (BATCH * SEQT)   // 8192
#define EPS_F 1e-6f
#define NCHUNK 32
#define CHUNK  (SEQT / NCHUNK)   // 128  (== M-tile, chunk-aligned)

// ---------------------------------------------------------------------------
// Scratch buffers (static; runtime allocation forbidden)
// ---------------------------------------------------------------------------
__device__ __align__(16) __half g_rh  [(size_t)MROWS * EMB];          //  16 MB
__device__ __align__(16) __half g_w12h[(size_t)(2 * HID) * EMB];      //  16 MB
__device__ __align__(16) __half g_w3h [(size_t)EMB * HID];            //   8 MB
__device__ __align__(16) __half g_ea  [(size_t)MROWS * HID];          //  64 MB exp(a)
__device__ __align__(16) __half g_eb  [(size_t)MROWS * HID];          //  64 MB exp(b)
__device__ __align__(16) __half g_y   [(size_t)MROWS * HID];          //  64 MB y=(sa*sb)/t^2
__device__ __align__(16) float g_pa[(size_t)BATCH * NCHUNK * HID];    //   1 MB
__device__ __align__(16) float g_pb[(size_t)BATCH * NCHUNK * HID];    //   1 MB
__device__ __align__(16) float g_scale[MROWS];                        //  32 KB row scales

// ---------------------------------------------------------------------------
// PTX helpers (plain sm_103-legal)
// ---------------------------------------------------------------------------
__device__ __forceinline__ uint32_t smem_u32(const void* p) {
    uint32_t a;
    asm("{ .reg .u64 t; cvta.to.shared.u64 t, %1; cvt.u32.u64 %0, t; }"
        : "=r"(a) : "l"(p));
    return a;
}
__device__ __forceinline__ void cp16(uint32_t s, const void* g) {
    asm volatile("cp.async.cg.shared.global [%0], [%1], 16;" :: "r"(s), "l"(g));
}
__device__ __forceinline__ void cp_commit() {
    asm volatile("cp.async.commit_group;" ::: "memory");
}
__device__ __forceinline__ void ldsm_x4(uint32_t& r0, uint32_t& r1,
                                        uint32_t& r2, uint32_t& r3, uint32_t addr) {
    asm volatile("ldmatrix.sync.aligned.m8n8.x4.shared.b16 {%0,%1,%2,%3}, [%4];"
                 : "=r"(r0), "=r"(r1), "=r"(r2), "=r"(r3) : "r"(addr));
}
__device__ __forceinline__ void mma16(float& d0, float& d1, float& d2, float& d3,
                                      uint32_t a0, uint32_t a1, uint32_t a2, uint32_t a3,
                                      uint32_t b0, uint32_t b1) {
    asm volatile(
        "mma.sync.aligned.m16n8k16.row.col.f32.f16.f16.f32 "
        "{%0,%1,%2,%3}, {%4,%5,%6,%7}, {%8,%9}, {%0,%1,%2,%3};"
        : "+f"(d0), "+f"(d1), "+f"(d2), "+f"(d3)
        : "r"(a0), "r"(a1), "r"(a2), "r"(a3), "r"(b0), "r"(b1));
}
__device__ __forceinline__ uint32_t sw128(uint32_t off) {
    return off ^ ((off >> 3) & 0x70);
}

// ===========================================================================
// Shared GEMM config: 128x128x64 tiles, 256 threads (8 warps 2x4), 2 CTA/SM.
// Mainloop: sync -> prefetch c+2 -> wait_group (prefetch issue hidden behind
// the wait for chunk c's data).
// ===========================================================================
#define BK 64
#define OPB 16384
#define STAGE_BYTES (2 * OPB)
#define NSTAGE 3
#define GEMM_SMEM (NSTAGE * STAGE_BYTES)

__device__ __forceinline__ void issue_tile_loads(
    uint32_t sbase, int st, const __half* Ab, const __half* Bb,
    int koff, int K, int tid)
{
    uint32_t stage = sbase + (uint32_t)st * STAGE_BYTES;
#pragma unroll
    for (int t = 0; t < 4; t++) {
        int idx = tid + t * 256;
        int row = idx >> 3;
        int u   = idx & 7;
        uint32_t sw = sw128((uint32_t)idx << 4);
        cp16(stage       + sw, Ab + (size_t)row * K + koff + u * 8);
        cp16(stage + OPB + sw, Bb + (size_t)row * K + koff + u * 8);
    }
}

// MODE 1: epilogue exp() -> fp16 E0/E1 + per-chunk column sums
// MODE 2: epilogue out = Cadd + S[m]*acc
template <int MODE>
__global__ void __launch_bounds__(256, 2)
hgemm_kernel(const __half* __restrict__ A, const __half* __restrict__ B,
             float* __restrict__ C0,
             const float* __restrict__ Cadd,
             __half* __restrict__ E0, __half* __restrict__ E1,
             float* __restrict__ pa, float* __restrict__ pb,
             const float* __restrict__ S,
             int M, int N, int K, int nsplit)
{
    extern __shared__ char smem[];
    uint32_t sbase = smem_u32(smem);
    const int tid  = threadIdx.x;
    const int wid  = tid >> 5;
    const int lane = tid & 31;
    const int wm   = wid & 1;
    const int wn   = wid >> 1;
    const int bm   = blockIdx.y * 128;
    const int bn   = blockIdx.x * 128;
    const int NC   = K / BK;

    const __half* Ab = A + (size_t)bm * K;
    const __half* Bb = B + (size_t)bn * K;

    float acc[4][4][4];
#pragma unroll
    for (int i = 0; i < 4; i++)
#pragma unroll
        for (int j = 0; j < 4; j++)
#pragma unroll
            for (int q = 0; q < 4; q++) acc[i][j][q] = 0.0f;

    const int a_m  = wm * 64 + (lane & 15);
    const int a_ku = lane >> 4;
    const int b_n  = wn * 32 + (lane & 7) + ((lane >> 4) << 3);
    const int b_ku = (lane >> 3) & 1;

    issue_tile_loads(sbase, 0, Ab, Bb, 0,  K, tid); cp_commit();
    issue_tile_loads(sbase, 1, Ab, Bb, BK, K, tid); cp_commit();

    for (int c = 0; c < NC; c++) {
        __syncthreads();   // stage (c+2)%3 free (consumed in iter c-1)

        if (c + 2 < NC) {
            issue_tile_loads(sbase, (c + 2) % NSTAGE, Ab, Bb, (c + 2) * BK, K, tid);
            cp_commit();
            asm volatile("cp.async.wait_group 2;" ::: "memory");  // chunk c landed
        } else if (c + 1 < NC) {
            asm volatile("cp.async.wait_group 1;" ::: "memory");
        } else {
            asm volatile("cp.async.wait_group 0;" ::: "memory");
        }
        __syncthreads();   // all warps see chunk c's data

        uint32_t stage = sbase + (uint32_t)(c % NSTAGE) * STAGE_BYTES;
#pragma unroll
        for (int ks = 0; ks < 4; ks++) {
            uint32_t a0[4], a1[4], a2[4], a3[4];
            uint32_t bb0[2], bb1[2], bb2[2], bb3[2];
#pragma unroll
            for (int mf = 0; mf < 4; mf++) {
                int m  = a_m + mf * 16;
                int ku = ks * 2 + a_ku;
                ldsm_x4(a0[mf], a1[mf], a2[mf], a3[mf],
                        stage + sw128((uint32_t)(m * 128 + ku * 16)));
            }
#pragma unroll
            for (int nf2 = 0; nf2 < 2; nf2++) {
                int n  = b_n + nf2 * 16;
                int ku = ks * 2 + b_ku;
                uint32_t r0, r1, r2, r3;
                ldsm_x4(r0, r1, r2, r3,
                        stage + OPB + sw128((uint32_t)(n * 128 + ku * 16)));
                if (nf2 == 0) { bb0[0] = r0; bb0[1] = r1; bb1[0] = r2; bb1[1] = r3; }
                else          { bb2[0] = r0; bb2[1] = r1; bb3[0] = r2; bb3[1] = r3; }
            }
#pragma unroll
            for (int mf = 0; mf < 4; mf++) {
                mma16(acc[mf][0][0], acc[mf][0][1], acc[mf][0][2], acc[mf][0][3],
                      a0[mf], a1[mf], a2[mf], a3[mf], bb0[0], bb0[1]);
                mma16(acc[mf][1][0], acc[mf][1][1], acc[mf][1][2], acc[mf][1][3],
                      a0[mf], a1[mf], a2[mf], a3[mf], bb1[0], bb1[1]);
                mma16(acc[mf][2][0], acc[mf][2][1], acc[mf][2][2], acc[mf][2][3],
                      a0[mf], a1[mf], a2[mf], a3[mf], bb2[0], bb2[1]);
                mma16(acc[mf][3][0], acc[mf][3][1], acc[mf][3][2], acc[mf][3][3],
                      a0[mf], a1[mf], a2[mf], a3[mf], bb3[0], bb3[1]);
            }
        }
    }

    const int inC0 = (bn < nsplit);
    const int ldc  = inC0 ? nsplit : (N - nsplit);
    const int cb   = inC0 ? bn : bn - nsplit;

    if (MODE == 2) {
#pragma unroll
        for (int mf = 0; mf < 4; mf++) {
            int r0 = bm + wm * 64 + mf * 16 + (lane >> 2);
            int r1 = r0 + 8;
            float s0 = S[r0], s1 = S[r1];
#pragma unroll
            for (int nf = 0; nf < 4; nf++) {
                int col = cb + wn * 32 + nf * 8 + (lane & 3) * 2;
                const float2 x0 = *(const float2*)(Cadd + (size_t)r0 * ldc + col);
                const float2 x1 = *(const float2*)(Cadd + (size_t)r1 * ldc + col);
                float2 v0 = make_float2(fmaf(s0, acc[mf][nf][0], x0.x),
                                        fmaf(s0, acc[mf][nf][1], x0.y));
                float2 v1 = make_float2(fmaf(s1, acc[mf][nf][2], x1.x),
                                        fmaf(s1, acc[mf][nf][3], x1.y));
                *(float2*)(C0 + (size_t)r0 * ldc + col) = v0;
                *(float2*)(C0 + (size_t)r1 * ldc + col) = v1;
            }
        }
    } else {
        // MODE 1: exp in place, store fp16, reduce per-chunk column sums
#pragma unroll
        for (int mf = 0; mf < 4; mf++)
#pragma unroll
            for (int nf = 0; nf < 4; nf++)
#pragma unroll
                for (int q = 0; q < 4; q++)
                    acc[mf][nf][q] = __expf(acc[mf][nf][q]);

        __half* Eb = inC0 ? E0 : E1;
#pragma unroll
        for (int mf = 0; mf < 4; mf++) {
            int r0 = bm + wm * 64 + mf * 16 + (lane >> 2);
            int r1 = r0 + 8;
#pragma unroll
            for (int nf = 0; nf < 4; nf++) {
                int col = cb + wn * 32 + nf * 8 + (lane & 3) * 2;
                *(__half2*)(Eb + (size_t)r0 * ldc + col) =
                    __floats2half2_rn(acc[mf][nf][0], acc[mf][nf][1]);
                *(__half2*)(Eb + (size_t)r1 * ldc + col) =
                    __floats2half2_rn(acc[mf][nf][2], acc[mf][nf][3]);
            }
        }

        float cs[4][2];
#pragma unroll
        for (int nf = 0; nf < 4; nf++) {
            cs[nf][0] = cs[nf][1] = 0.0f;
#pragma unroll
            for (int mf = 0; mf < 4; mf++) {
                cs[nf][0] += acc[mf][nf][0] + acc[mf][nf][2];
                cs[nf][1] += acc[mf][nf][1] + acc[mf][nf][3];
            }
#pragma unroll
            for (int off = 4; off < 32; off <<= 1) {
                cs[nf][0] += __shfl_xor_sync(0xffffffffu, cs[nf][0], off);
                cs[nf][1] += __shfl_xor_sync(0xffffffffu, cs[nf][1], off);
            }
        }
        __syncthreads();             // mainloop smem use done block-wide
        float* red = (float*)smem;   // stages dead now
        if (lane < 4) {
#pragma unroll
            for (int nf = 0; nf < 4; nf++) {
                int col = wn * 32 + nf * 8 + lane * 2;
                red[wm * 128 + col]     = cs[nf][0];
                red[wm * 128 + col + 1] = cs[nf][1];
            }
        }
        __syncthreads();
        if (tid < 128) {
            int bb = bm / SEQT;
            int ch = (bm % SEQT) / CHUNK;
            float* P = inC0 ? pa : pb;
            P[(size_t)(bb * NCHUNK + ch) * HID + cb + tid] =
                red[tid] + red[128 + tid];
        }
    }
}

// ---------------------------------------------------------------------------
// Block-wide sum reduce
// ---------------------------------------------------------------------------
__device__ __forceinline__ float block_reduce_sum(float v) {
    __shared__ float sh[32];
    int lane = threadIdx.x & 31;
    int wid  = threadIdx.x >> 5;
#pragma unroll
    for (int o = 16; o; o >>= 1) v += __shfl_xor_sync(0xffffffffu, v, o);
    if (lane == 0) sh[wid] = v;
    __syncthreads();
    int nw = blockDim.x >> 5;
    if (wid == 0) {
        v = (lane < nw) ? sh[lane] : 0.0f;
#pragma unroll
        for (int o = 16; o; o >>= 1) v += __shfl_xor_sync(0xffffffffu, v, o);
    }
    return v;
}

// ---------------------------------------------------------------------------
// Fused prep: blocks [0, MROWS) do rmsnorm(x)->fp16; remaining blocks convert
// W1/W2/W3 fp32->fp16 (256 float4s per block).
// ---------------------------------------------------------------------------
__global__ void prep_kernel(const float* __restrict__ x,
                            const float* __restrict__ W1,
                            const float* __restrict__ W2,
                            const float* __restrict__ W3,
                            __half* __restrict__ rh,
                            __half* __restrict__ w12h,
                            __half* __restrict__ w3h,
                            int nv12, int nv3) {
    if (blockIdx.x < MROWS) {
        int row = blockIdx.x;
        const float4* ir = (const float4*)(x + (size_t)row * EMB);
        int nvec = EMB >> 2;
        float ss = 0.0f;
        for (int i = threadIdx.x; i < nvec; i += 256) {
            float4 v = ir[i];
            ss += v.x * v.x + v.y * v.y + v.z * v.z + v.w * v.w;
        }
        ss = block_reduce_sum(ss);
        __shared__ float s_scale;
        if (threadIdx.x == 0) s_scale = rsqrtf(ss / (float)EMB + EPS_F);
        __syncthreads();
        float sc = s_scale;
        __half2* op = (__half2*)(rh + (size_t)row * EMB);
        for (int i = threadIdx.x; i < nvec; i += 256) {
            float4 v = ir[i];
            op[2 * i]     = __floats2half2_rn(v.x * sc, v.y * sc);
            op[2 * i + 1] = __floats2half2_rn(v.z * sc, v.w * sc);
        }
    } else {
        int i = (blockIdx.x - MROWS) * 256 + threadIdx.x;
        const float* src;
        __half2* dst;
        int j;
        if (i < nv12)                { src = W1; dst = (__half2*)w12h;                      j = i; }
        else if (i < 2 * nv12)       { src = W2; dst = (__half2*)(w12h + (size_t)nv12 * 4); j = i - nv12; }
        else if (i < 2 * nv12 + nv3) { src = W3; dst = (__half2*)w3h;                      j = i - 2 * nv12; }
        else return;
        float4 v = ((const float4*)src)[j];
        dst[2 * j]     = __floats2half2_rn(v.x, v.y);
        dst[2 * j + 1] = __floats2half2_rn(v.z, v.w);
    }
}

// ---------------------------------------------------------------------------
// Row rms-scale from fp16 y: scale[row] = rsqrt(mean(y^2) + eps)
// ---------------------------------------------------------------------------
__global__ void rowscale_kernel(const __half* __restrict__ y,
                                float* __restrict__ scale) {
    int row = blockIdx.x;
    const float4* ir = (const float4*)(y + (size_t)row * HID);  // 8 halves per ld
    float ss = 0.0f;
    for (int i = threadIdx.x; i < HID / 8; i += 256) {
        float4 u = ir[i];
        __half2 h0 = *(__half2*)&u.x, h1 = *(__half2*)&u.y;
        __half2 h2 = *(__half2*)&u.z, h3 = *(__half2*)&u.w;
        float2 v0 = __half22float2(h0), v1 = __half22float2(h1);
        float2 v2 = __half22float2(h2), v3 = __half22float2(h3);
        ss += v0.x * v0.x + v0.y * v0.y + v1.x * v1.x + v1.y * v1.y
            + v2.x * v2.x + v2.y * v2.y + v3.x * v3.x + v3.y * v3.y;
    }
    ss = block_reduce_sum(ss);
    if (threadIdx.x == 0) scale[row] = rsqrtf(ss / (float)HID + EPS_F);
}

// ---------------------------------------------------------------------------
// pass2: exclusive prefix over chunk sums (batched loads for MLP)
// ---------------------------------------------------------------------------
__global__ void bar_pass2_kernel(float* __restrict__ pa,
                                 float* __restrict__ pb) {
    int idx = blockIdx.x * 256 + threadIdx.x;
    int bb = idx >> 12;
    int h  = idx & (HID - 1);
    float va[NCHUNK], vb[NCHUNK];
#pragma unroll
    for (int c = 0; c < NCHUNK; c++) {
        va[c] = pa[(size_t)(bb * NCHUNK + c) * HID + h];
        vb[c] = pb[(size_t)(bb * NCHUNK + c) * HID + h];
    }
    float ra = 0.0f, rb = 0.0f;
#pragma unroll
    for (int c = 0; c < NCHUNK; c++) {
        float ta = va[c], tb = vb[c];
        va[c] = ra; vb[c] = rb;
        ra += ta; rb += tb;
    }
#pragma unroll
    for (int c = 0; c < NCHUNK; c++) {
        pa[(size_t)(bb * NCHUNK + c) * HID + h] = va[c];
        pb[(size_t)(bb * NCHUNK + c) * HID + h] = vb[c];
    }
}

// ---------------------------------------------------------------------------
// pass3: within-chunk scan from prefix; y = (sa*sb)/(t+1)^2 in fp16.
// 128-thread blocks, 1024 blocks (6.9 waves -> minimal tail quantization).
// Pure streaming, 2 channels per thread.
// ---------------------------------------------------------------------------
__global__ void bar_pass3_kernel(const __half* __restrict__ ea,
                                 const __half* __restrict__ eb,
                                 const float* __restrict__ pa,
                                 const float* __restrict__ pb,
                                 __half* __restrict__ y) {
    int h2 = blockIdx.x * 128 + threadIdx.x;   // pair index
    int c  = blockIdx.y;
    int bb = blockIdx.z;
    size_t base = (size_t)bb * SEQT * HID + (size_t)c * CHUNK * HID + h2 * 2;
    const __half2* ap = (const __half2*)(ea + base);
    const __half2* bp = (const __half2*)(eb + base);
    __half2* yp = (__half2*)(y + base);

    int po = (bb * NCHUNK + c) * HID + h2 * 2;
    float sa0 = pa[po], sa1 = pa[po + 1];
    float sb0 = pb[po], sb1 = pb[po + 1];
#pragma unroll 8
    for (int t = 0; t < CHUNK; t++) {
        float2 va = __half22float2(ap[(size_t)t * (HID / 2)]);
        float2 vb = __half22float2(bp[(size_t)t * (HID / 2)]);
        sa0 += va.x; sa1 += va.y;
        sb0 += vb.x; sb1 += vb.y;
        float tf = (float)(c * CHUNK + t + 1);
        float inv = __fdividef(1.0f, tf * tf);
        yp[(size_t)t * (HID / 2)] =
            __floats2half2_rn(sa0 * sb0 * inv, sa1 * sb1 * inv);
    }
}

// ---------------------------------------------------------------------------
// kernel_launch
// ---------------------------------------------------------------------------
extern "C" void kernel_launch(void* const* d_in, const int* in_sizes, int n_in,
                              void* d_out, int out_size) {
    const float* x  = (const float*)d_in[0];
    const float* W1 = (const float*)d_in[1];
    const float* W2 = (const float*)d_in[2];
    const float* W3 = (const float*)d_in[3];
    float* out = (float*)d_out;

    __half *rh, *w12h, *w3h, *ea, *eb, *y_p;
    float *pa_p, *pb_p, *sc_p;
    cudaGetSymbolAddress((void**)&rh,   g_rh);
    cudaGetSymbolAddress((void**)&w12h, g_w12h);
    cudaGetSymbolAddress((void**)&w3h,  g_w3h);
    cudaGetSymbolAddress((void**)&ea,   g_ea);
    cudaGetSymbolAddress((void**)&eb,   g_eb);
    cudaGetSymbolAddress((void**)&y_p,  g_y);
    cudaGetSymbolAddress((void**)&pa_p, g_pa);
    cudaGetSymbolAddress((void**)&pb_p, g_pb);
    cudaGetSymbolAddress((void**)&sc_p, g_scale);

    cudaFuncSetAttribute(hgemm_kernel<1>, cudaFuncAttributeMaxDynamicSharedMemorySize,
                         GEMM_SMEM);
    cudaFuncSetAttribute(hgemm_kernel<2>, cudaFuncAttributeMaxDynamicSharedMemorySize,
                         GEMM_SMEM);

    // 1) fused prep: rmsnorm(x)->fp16 + all weight converts, one launch
    {
        int nv12 = (HID * EMB) / 4;
        int nv3  = (EMB * HID) / 4;
        int wblocks = (2 * nv12 + nv3 + 255) / 256;
        prep_kernel<<<MROWS + wblocks, 256>>>(x, W1, W2, W3, rh, w12h, w3h,
                                              nv12, nv3);
    }

    // 2) fused GEMM1/2 + exp + chunk sums (128x128, 2 CTA/SM)
    hgemm_kernel<1><<<dim3((2 * HID) / 128, MROWS / 128), 256, GEMM_SMEM>>>(
        rh, w12h, nullptr, nullptr, ea, eb, pa_p, pb_p, nullptr,
        MROWS, 2 * HID, EMB, HID);

    // 3) prefix over chunks, then within-chunk streaming scan -> y fp16
    bar_pass2_kernel<<<(BATCH * HID) / 256, 256>>>(pa_p, pb_p);
    {
        dim3 grid(HID / 256, NCHUNK, BATCH);   // 16 x 32 x 2 = 1024 blocks
        bar_pass3_kernel<<<grid, 128>>>(ea, eb, pa_p, pb_p, y_p);
    }

    // 4) per-row rms scales from y
    rowscale_kernel<<<MROWS, 256>>>(y_p, sc_p);

    // 5) out = x + S[m] * (y @ W3^T)
    hgemm_kernel<2><<<dim3(EMB / 128, MROWS / 128), 256, GEMM_SMEM>>>(
        y_p, w3h, out, x, nullptr, nullptr, nullptr, nullptr, sc_p,
        MROWS, EMB, HID, EMB);
}